// round 1
// baseline (speedup 1.0000x reference)
#include <cuda_runtime.h>
#include <stdint.h>

#define BATCH 2048
#define KTOP  32
#define DDIM  768
#define DICT  24576
#define CONN  64

// bias contribution table: b_dec_contrib[f] = dot(up_encoder_w[f,:], b_dec)
__device__ float g_bias[DICT];

// ---------------------------------------------------------------------------
// Kernel A: b_dec_contrib = up_encoder_w @ b_dec   (warp per row, float4 loads)
// ---------------------------------------------------------------------------
__global__ __launch_bounds__(256) void bias_kernel(
    const float* __restrict__ up_encoder_w,   // [DICT, D]
    const float* __restrict__ b_dec)          // [D]
{
    __shared__ float s_b[DDIM];
    for (int i = threadIdx.x; i < DDIM; i += blockDim.x) s_b[i] = b_dec[i];
    __syncthreads();

    int warp = threadIdx.x >> 5;
    int lane = threadIdx.x & 31;
    int row  = blockIdx.x * (blockDim.x >> 5) + warp;
    if (row >= DICT) return;

    const float4* w  = reinterpret_cast<const float4*>(up_encoder_w + (size_t)row * DDIM);
    const float4* bb = reinterpret_cast<const float4*>(s_b);
    float acc = 0.f;
#pragma unroll
    for (int k = 0; k < DDIM / 128; k++) {           // 6 iterations
        float4 v = w[lane + 32 * k];
        float4 b = bb[lane + 32 * k];
        acc += v.x * b.x + v.y * b.y + v.z * b.z + v.w * b.w;
    }
#pragma unroll
    for (int o = 16; o > 0; o >>= 1) acc += __shfl_xor_sync(0xffffffffu, acc, o);
    if (lane == 0) g_bias[row] = acc;
}

// ---------------------------------------------------------------------------
// Kernel B: sparse virtual-weight contributions. One block per batch element.
// ---------------------------------------------------------------------------
#define HSZ 64   // hash table slots (power of two, load factor 0.5)

__global__ __launch_bounds__(128) void main_kernel(
    const float* __restrict__ up_vals,        // [B, K]
    const float* __restrict__ up_decoder_w,   // [D, DICT]
    const float* __restrict__ down_encoder_w, // [DICT, D]
    const int*   __restrict__ up_indices,     // [B, K]
    const int*   __restrict__ down_indices,   // [B, K]
    const int*   __restrict__ connections,    // [DICT, C]
    float*       __restrict__ out)            // [B, K]
{
    __shared__ int   s_up_idx[KTOP];
    __shared__ float s_up_val[KTOP];
    __shared__ int   s_down_idx[KTOP];
    __shared__ float s_acc[KTOP];
    __shared__ int   s_hkey[HSZ];
    __shared__ int   s_hj[HSZ];
    __shared__ int   s_mult[KTOP * KTOP];
    __shared__ int   s_pairs[KTOP * KTOP];
    __shared__ int   s_npairs;

    const int b = blockIdx.x;
    const int t = threadIdx.x;

    if (t < KTOP) {
        s_up_idx[t]   = up_indices[b * KTOP + t];
        s_up_val[t]   = up_vals[b * KTOP + t];
        s_down_idx[t] = down_indices[b * KTOP + t];
        s_acc[t]      = 0.f;
    }
    if (t < HSZ) s_hkey[t] = -1;
    if (t == 0)  s_npairs = 0;
    for (int e = t; e < KTOP * KTOP; e += blockDim.x) s_mult[e] = 0;
    __syncthreads();

    // Build hash table of up indices (duplicates each get their own slot).
    if (t < KTOP) {
        int key = s_up_idx[t];
        unsigned p = ((unsigned)key * 2654435761u) >> 26;  // 6-bit hash
        while (true) {
            int old = atomicCAS(&s_hkey[p & (HSZ - 1)], -1, key);
            if (old == -1) { s_hj[p & (HSZ - 1)] = t; break; }
            p++;
        }
    }
    __syncthreads();

    // Matching: 32 downstream features x 16 int4 connection chunks = 512 items.
    for (int item = t; item < KTOP * (CONN / 4); item += blockDim.x) {
        int i = item >> 4;
        int q = item & 15;
        int di = s_down_idx[i];
        int4 a = reinterpret_cast<const int4*>(connections + (size_t)di * CONN)[q];
        int av[4] = {a.x, a.y, a.z, a.w};
#pragma unroll
        for (int s = 0; s < 4; s++) {
            int v = av[s];
            if (v < 0) continue;
            unsigned p = ((unsigned)v * 2654435761u) >> 26;
            while (true) {
                int k = s_hkey[p & (HSZ - 1)];
                if (k == -1) break;
                if (k == v) atomicAdd(&s_mult[i * KTOP + s_hj[p & (HSZ - 1)]], 1);
                p++;
            }
        }
    }
    __syncthreads();

    // Compact nonzero (i,j) pairs.
    for (int e = t; e < KTOP * KTOP; e += blockDim.x) {
        if (s_mult[e] != 0) {
            int p = atomicAdd(&s_npairs, 1);
            s_pairs[p] = e;
        }
    }
    __syncthreads();

    // Warp-per-pair 768-length dot products.
    const int npairs = s_npairs;
    const int warp = t >> 5;
    const int lane = t & 31;
    for (int p = warp; p < npairs; p += 4) {
        int e  = s_pairs[p];
        int i  = e >> 5;
        int j  = e & 31;
        int di = s_down_idx[i];
        int uj = s_up_idx[j];
        const float* drow = down_encoder_w + (size_t)di * DDIM;  // coalesced
        const float* ucol = up_decoder_w + uj;                   // stride DICT
        float acc = 0.f;
#pragma unroll
        for (int k = 0; k < DDIM / 32; k++) {                    // 24 indep loads
            int d = lane + 32 * k;
            acc += drow[d] * ucol[(size_t)d * DICT];
        }
#pragma unroll
        for (int o = 16; o > 0; o >>= 1) acc += __shfl_xor_sync(0xffffffffu, acc, o);
        if (lane == 0)
            atomicAdd(&s_acc[i], acc * (float)s_mult[e] * s_up_val[j]);
    }
    __syncthreads();

    if (t < KTOP)
        out[b * KTOP + t] = s_acc[t] + g_bias[s_up_idx[t]];
}

// ---------------------------------------------------------------------------
extern "C" void kernel_launch(void* const* d_in, const int* in_sizes, int n_in,
                              void* d_out, int out_size)
{
    const float* up_vals        = (const float*)d_in[0];
    const float* up_decoder_w   = (const float*)d_in[1];
    const float* down_encoder_w = (const float*)d_in[2];
    const float* up_encoder_w   = (const float*)d_in[3];
    const float* b_dec          = (const float*)d_in[4];
    const int*   up_indices     = (const int*)d_in[5];
    const int*   down_indices   = (const int*)d_in[6];
    const int*   connections    = (const int*)d_in[7];
    float*       out            = (float*)d_out;

    bias_kernel<<<DICT / 8, 256>>>(up_encoder_w, b_dec);
    main_kernel<<<BATCH, 128>>>(up_vals, up_decoder_w, down_encoder_w,
                                up_indices, down_indices, connections, out);
}